// round 1
// baseline (speedup 1.0000x reference)
#include <cuda_runtime.h>
#include <math.h>

// ---------------------------------------------------------------------------
// Problem constants
// ---------------------------------------------------------------------------
#define NNODES  10000
#define NHEDGES 512
#define EDIM    128     // N_DIM == HE_DIM == DIM == 128
#define TOPK    32
#define ALPHA   3.0f

// ---------------------------------------------------------------------------
// Scratch (device globals -- no runtime allocation allowed)
// ---------------------------------------------------------------------------
__device__ float g_nv1[NNODES * EDIM];     // tanh(3*(embn[idx]@W1+b1))   [10000,128]
__device__ float g_nv2[NHEDGES * EDIM];    // tanh(3*(embhe@W2+b2))       [512,128]
__device__ float g_H[NNODES * NHEDGES];    // relu(tanh(3*nv1@nv2^T))     [10000,512]

// ---------------------------------------------------------------------------
// Kernel 1: nodevec = tanh(ALPHA*(emb[row]@W + b)), one block per row,
// 128 threads, thread d owns output column d.
// ---------------------------------------------------------------------------
__global__ void __launch_bounds__(EDIM) nodevec_kernel(
    const float* __restrict__ emb,
    const int*   __restrict__ idx,      // may be nullptr (identity)
    const float* __restrict__ W,        // [EDIM, EDIM] row-major
    const float* __restrict__ b,        // [EDIM]
    float*       __restrict__ out)      // [rows, EDIM]
{
    __shared__ float s_in[EDIM];
    const int r   = blockIdx.x;
    const int d   = threadIdx.x;
    const int src = idx ? idx[r] : r;
    s_in[d] = emb[(size_t)src * EDIM + d];
    __syncthreads();

    float acc = b[d];
#pragma unroll 8
    for (int k = 0; k < EDIM; k++)
        acc = fmaf(s_in[k], W[k * EDIM + d], acc);

    out[(size_t)r * EDIM + d] = tanhf(ALPHA * acc);
}

// ---------------------------------------------------------------------------
// Kernel 2/3: C[M,N] = act( A[M,K] @ B[N,K]^T )
// Classic SIMT fp32 GEMM: 128x128 block tile, BK=16, 256 threads, 8x8/thread,
// double-buffered SMEM. EPI==0: identity (adj). EPI==1: relu(tanh(3x)) (H).
// Requires: K % 16 == 0, N % 4 == 0, rows of A/B/C 16B-aligned.
// ---------------------------------------------------------------------------
#define GT_TM 128
#define GT_BK 16

template<int EPI>
__global__ void __launch_bounds__(256, 2) gemm_nt_kernel(
    const float* __restrict__ A,
    const float* __restrict__ B,
    float*       __restrict__ C,
    int M, int N, int Kd)
{
    __shared__ __align__(16) float As[2][GT_BK][GT_TM];
    __shared__ __align__(16) float Bs[2][GT_BK][GT_TM];

    const int tid = threadIdx.x;
    const int bm  = blockIdx.y * GT_TM;
    const int bn  = blockIdx.x * GT_TM;
    const int tx  = tid & 15;   // column group (8 cols)
    const int ty  = tid >> 4;   // row group (8 rows)

    float acc[8][8];
#pragma unroll
    for (int i = 0; i < 8; i++)
#pragma unroll
        for (int j = 0; j < 8; j++) acc[i][j] = 0.0f;

    auto stage = [&](int buf, int k0) {
#pragma unroll
        for (int s = 0; s < 2; s++) {
            const int f  = tid + s * 256;        // 0..511
            const int r  = f >> 2;               // 0..127
            const int kq = (f & 3) << 2;         // 0,4,8,12
            const int ga = bm + r;
            float4 va = make_float4(0.f, 0.f, 0.f, 0.f);
            if (ga < M)
                va = *reinterpret_cast<const float4*>(A + (size_t)ga * Kd + k0 + kq);
            As[buf][kq + 0][r] = va.x; As[buf][kq + 1][r] = va.y;
            As[buf][kq + 2][r] = va.z; As[buf][kq + 3][r] = va.w;

            const int gb = bn + r;
            float4 vb = make_float4(0.f, 0.f, 0.f, 0.f);
            if (gb < N)
                vb = *reinterpret_cast<const float4*>(B + (size_t)gb * Kd + k0 + kq);
            Bs[buf][kq + 0][r] = vb.x; Bs[buf][kq + 1][r] = vb.y;
            Bs[buf][kq + 2][r] = vb.z; Bs[buf][kq + 3][r] = vb.w;
        }
    };

    stage(0, 0);
    __syncthreads();

    const int nk = Kd / GT_BK;
    for (int kt = 0; kt < nk; kt++) {
        const int cur = kt & 1;
        if (kt + 1 < nk) stage(cur ^ 1, (kt + 1) * GT_BK);

#pragma unroll
        for (int kk = 0; kk < GT_BK; kk++) {
            float a[8], b[8];
#pragma unroll
            for (int i = 0; i < 8; i += 4)
                *reinterpret_cast<float4*>(&a[i]) =
                    *reinterpret_cast<const float4*>(&As[cur][kk][ty * 8 + i]);
#pragma unroll
            for (int j = 0; j < 8; j += 4)
                *reinterpret_cast<float4*>(&b[j]) =
                    *reinterpret_cast<const float4*>(&Bs[cur][kk][tx * 8 + j]);
#pragma unroll
            for (int i = 0; i < 8; i++)
#pragma unroll
                for (int j = 0; j < 8; j++)
                    acc[i][j] = fmaf(a[i], b[j], acc[i][j]);
        }
        __syncthreads();
    }

    // epilogue
#pragma unroll
    for (int i = 0; i < 8; i++) {
        const int gr = bm + ty * 8 + i;
        if (gr >= M) continue;
        float* crow = C + (size_t)gr * N;
#pragma unroll
        for (int j = 0; j < 8; j += 4) {
            const int gc = bn + tx * 8 + j;
            float4 v;
            if (EPI == 1) {
                v.x = fmaxf(tanhf(ALPHA * acc[i][j + 0]), 0.0f);
                v.y = fmaxf(tanhf(ALPHA * acc[i][j + 1]), 0.0f);
                v.z = fmaxf(tanhf(ALPHA * acc[i][j + 2]), 0.0f);
                v.w = fmaxf(tanhf(ALPHA * acc[i][j + 3]), 0.0f);
            } else {
                v.x = acc[i][j + 0]; v.y = acc[i][j + 1];
                v.z = acc[i][j + 2]; v.w = acc[i][j + 3];
            }
            if (gc + 3 < N) {
                *reinterpret_cast<float4*>(crow + gc) = v;
            } else {
                const float vv[4] = {v.x, v.y, v.z, v.w};
                for (int q = 0; q < 4; q++)
                    if (gc + q < N) crow[gc + q] = vv[q];
            }
        }
    }
}

// ---------------------------------------------------------------------------
// Kernel 4: per-row top-K mask, in place on adj. One block (256 thr) per row.
// Row staged in SMEM; 4-pass MSB radix select on float bits (adj >= 0, so the
// uint bit pattern is order-preserving). Exactly reproduces jax.lax.top_k
// tie-breaking (lowest index first) via the rare serial-prune path.
// ---------------------------------------------------------------------------
__global__ void __launch_bounds__(256) topk_mask_kernel(float* __restrict__ adj, int N)
{
    __shared__ float    s_val[NNODES];
    __shared__ unsigned s_hist[256];
    __shared__ unsigned s_prefix;
    __shared__ int      s_rank, s_cnt;

    const int    tid  = threadIdx.x;
    const size_t base = (size_t)blockIdx.x * N;

    for (int j = tid; j < N; j += 256) s_val[j] = adj[base + j];
    __syncthreads();

    unsigned prefix = 0u;
    int      rank   = TOPK;   // looking for the rank-th largest (1-based)
    int      cnt_eq = 0;

    for (int shift = 24; shift >= 0; shift -= 8) {
        s_hist[tid & 255] = 0;     // 256 threads, each zeroes one bin
        __syncthreads();

        const unsigned hmask = (shift == 24) ? 0u : (0xFFFFFFFFu << (shift + 8));
        for (int j = tid; j < N; j += 256) {
            const unsigned k = __float_as_uint(s_val[j]);
            if ((k & hmask) == prefix)
                atomicAdd(&s_hist[(k >> shift) & 0xFF], 1u);
        }
        __syncthreads();

        if (tid == 0) {
            int r = rank;
            int b = 255;
            for (;; b--) {
                const int h = (int)s_hist[b];
                if (h >= r || b == 0) { s_cnt = h; break; }
                r -= h;
            }
            s_prefix = prefix | ((unsigned)b << shift);
            s_rank   = r;
        }
        __syncthreads();
        prefix = s_prefix;
        rank   = s_rank;
        cnt_eq = s_cnt;
        __syncthreads();
    }

    const float Tval = __uint_as_float(prefix);

    if (cnt_eq > rank) {
        // ties at the threshold: keep only the first `rank` of them (by index),
        // demote the rest below the threshold. Rare path.
        if (tid == 0) {
            int kept = 0;
            for (int j = 0; j < N; j++) {
                if (__float_as_uint(s_val[j]) == prefix) {
                    kept++;
                    if (kept > rank) s_val[j] = -1.0f;
                }
            }
        }
        __syncthreads();
    }

    for (int j = tid; j < N; j += 256) {
        const float v = s_val[j];
        adj[base + j] = (v >= Tval) ? v : 0.0f;
    }
}

// ---------------------------------------------------------------------------
// kernel_launch
// Inputs (metadata order): idx(i32,10000) embn(f32,10000x128) embhe(f32,512x128)
//                          W1(f32,128x128) b1(f32,128) W2(f32,128x128) b2(f32,128)
// Output: adj*mask  (f32, 10000x10000)
// ---------------------------------------------------------------------------
extern "C" void kernel_launch(void* const* d_in, const int* in_sizes, int n_in,
                              void* d_out, int out_size)
{
    (void)in_sizes; (void)n_in; (void)out_size;

    const int*   idx   = (const int*)  d_in[0];
    const float* embn  = (const float*)d_in[1];
    const float* embhe = (const float*)d_in[2];
    const float* W1    = (const float*)d_in[3];
    const float* b1    = (const float*)d_in[4];
    const float* W2    = (const float*)d_in[5];
    const float* b2    = (const float*)d_in[6];
    float*       out   = (float*)d_out;

    float *p_nv1 = nullptr, *p_nv2 = nullptr, *p_H = nullptr;
    cudaGetSymbolAddress((void**)&p_nv1, g_nv1);
    cudaGetSymbolAddress((void**)&p_nv2, g_nv2);
    cudaGetSymbolAddress((void**)&p_H,   g_H);

    // 1) nodevec1 = tanh(3*(embn[idx] @ W1 + b1))      [10000,128]
    nodevec_kernel<<<NNODES, EDIM>>>(embn, idx, W1, b1, p_nv1);
    // 2) nodevec2 = tanh(3*(embhe @ W2 + b2))          [512,128]
    nodevec_kernel<<<NHEDGES, EDIM>>>(embhe, nullptr, W2, b2, p_nv2);

    // 3) H = relu(tanh(3 * nv1 @ nv2^T))               [10000,512]
    {
        dim3 grid((NHEDGES + GT_TM - 1) / GT_TM, (NNODES + GT_TM - 1) / GT_TM);
        gemm_nt_kernel<1><<<grid, 256>>>(p_nv1, p_nv2, p_H, NNODES, NHEDGES, EDIM);
    }

    // 4) adj = H @ H^T                                 [10000,10000] -> d_out
    {
        dim3 grid((NNODES + GT_TM - 1) / GT_TM, (NNODES + GT_TM - 1) / GT_TM);
        gemm_nt_kernel<0><<<grid, 256>>>(p_H, p_H, out, NNODES, NNODES, NHEDGES);
    }

    // 5) per-row top-32 mask, in place
    topk_mask_kernel<<<NNODES, 256>>>(out, NNODES);
}

// round 4
// speedup vs baseline: 1.5652x; 1.5652x over previous
#include <cuda_runtime.h>
#include <math.h>

// ---------------------------------------------------------------------------
// Problem constants
// ---------------------------------------------------------------------------
#define NNODES  10000
#define NHEDGES 512
#define EDIM    128
#define TOPK    32
#define ALPHA   3.0f

// ---------------------------------------------------------------------------
// Scratch (device globals -- no runtime allocation allowed)
// ---------------------------------------------------------------------------
__device__ float g_nv1[NNODES * EDIM];
__device__ float g_nv2[NHEDGES * EDIM];
__device__ float g_H[NNODES * NHEDGES];

// ---------------------------------------------------------------------------
// Kernel 1: nodevec = tanh(ALPHA*(emb[row]@W + b))
// ---------------------------------------------------------------------------
__global__ void __launch_bounds__(EDIM) nodevec_kernel(
    const float* __restrict__ emb,
    const int*   __restrict__ idx,
    const float* __restrict__ W,
    const float* __restrict__ b,
    float*       __restrict__ out)
{
    __shared__ float s_in[EDIM];
    const int r   = blockIdx.x;
    const int d   = threadIdx.x;
    const int src = idx ? idx[r] : r;
    s_in[d] = emb[(size_t)src * EDIM + d];
    __syncthreads();

    float acc = b[d];
#pragma unroll 8
    for (int k = 0; k < EDIM; k++)
        acc = fmaf(s_in[k], W[k * EDIM + d], acc);

    out[(size_t)r * EDIM + d] = tanhf(ALPHA * acc);
}

// ---------------------------------------------------------------------------
// Kernel 2: H = relu(tanh(3 * nv1 @ nv2^T))  -- identical mainloop to R1.
// ---------------------------------------------------------------------------
#define GT_TM 128
#define GT_BK 16

__global__ void __launch_bounds__(256, 2) h_gemm_kernel(
    const float* __restrict__ A,
    const float* __restrict__ B,
    float*       __restrict__ C,
    int M, int N, int Kd)
{
    __shared__ __align__(16) float As[2][GT_BK][GT_TM];
    __shared__ __align__(16) float Bs[2][GT_BK][GT_TM];

    const int tid = threadIdx.x;
    const int bm  = blockIdx.y * GT_TM;
    const int bn  = blockIdx.x * GT_TM;
    const int tx  = tid & 15;
    const int ty  = tid >> 4;

    float acc[8][8];
#pragma unroll
    for (int i = 0; i < 8; i++)
#pragma unroll
        for (int j = 0; j < 8; j++) acc[i][j] = 0.0f;

    auto stage = [&](int buf, int k0) {
#pragma unroll
        for (int s = 0; s < 2; s++) {
            const int f  = tid + s * 256;
            const int r  = f >> 2;
            const int kq = (f & 3) << 2;
            const int ga = bm + r;
            float4 va = make_float4(0.f, 0.f, 0.f, 0.f);
            if (ga < M)
                va = *reinterpret_cast<const float4*>(A + (size_t)ga * Kd + k0 + kq);
            As[buf][kq + 0][r] = va.x; As[buf][kq + 1][r] = va.y;
            As[buf][kq + 2][r] = va.z; As[buf][kq + 3][r] = va.w;

            const int gb = bn + r;
            float4 vb = make_float4(0.f, 0.f, 0.f, 0.f);
            if (gb < N)
                vb = *reinterpret_cast<const float4*>(B + (size_t)gb * Kd + k0 + kq);
            Bs[buf][kq + 0][r] = vb.x; Bs[buf][kq + 1][r] = vb.y;
            Bs[buf][kq + 2][r] = vb.z; Bs[buf][kq + 3][r] = vb.w;
        }
    };

    stage(0, 0);
    __syncthreads();

    const int nk = Kd / GT_BK;
    for (int kt = 0; kt < nk; kt++) {
        const int cur = kt & 1;
        if (kt + 1 < nk) stage(cur ^ 1, (kt + 1) * GT_BK);

#pragma unroll
        for (int kk = 0; kk < GT_BK; kk++) {
            float a[8], b[8];
#pragma unroll
            for (int i = 0; i < 8; i += 4)
                *reinterpret_cast<float4*>(&a[i]) =
                    *reinterpret_cast<const float4*>(&As[cur][kk][ty * 8 + i]);
#pragma unroll
            for (int j = 0; j < 8; j += 4)
                *reinterpret_cast<float4*>(&b[j]) =
                    *reinterpret_cast<const float4*>(&Bs[cur][kk][tx * 8 + j]);
#pragma unroll
            for (int i = 0; i < 8; i++)
#pragma unroll
                for (int j = 0; j < 8; j++)
                    acc[i][j] = fmaf(a[i], b[j], acc[i][j]);
        }
        __syncthreads();
    }

#pragma unroll
    for (int i = 0; i < 8; i++) {
        const int gr = bm + ty * 8 + i;
        if (gr >= M) continue;
        float* crow = C + (size_t)gr * N;
#pragma unroll
        for (int j = 0; j < 8; j += 4) {
            const int gc = bn + tx * 8 + j;
            float4 v;
            v.x = fmaxf(tanhf(ALPHA * acc[i][j + 0]), 0.0f);
            v.y = fmaxf(tanhf(ALPHA * acc[i][j + 1]), 0.0f);
            v.z = fmaxf(tanhf(ALPHA * acc[i][j + 2]), 0.0f);
            v.w = fmaxf(tanhf(ALPHA * acc[i][j + 3]), 0.0f);
            if (gc + 3 < N) {
                *reinterpret_cast<float4*>(crow + gc) = v;
            } else {
                const float vv[4] = {v.x, v.y, v.z, v.w};
                for (int q = 0; q < 4; q++)
                    if (gc + q < N) crow[gc + q] = vv[q];
            }
        }
    }
}

// ---------------------------------------------------------------------------
// Kernel 3: adj = H @ H^T, fp32 FFMA, bit-identical accumulation to R1
// (sequential k ascending per entry). Symmetry: only bx >= by tiles are
// computed; the mirror tile is written via a padded SMEM transpose.
// Dynamic SMEM layout (union over time):
//   phase 1 (mainloop): As[2][16][128], Bs[2][16][128]   (32 KB)
//   phase 2 (epilogue): Ct[128][133] floats              (68,096 B)
// ---------------------------------------------------------------------------
#define ADJ_SMEM_BYTES (128 * 133 * 4)   // 68096 >= 32768

__global__ void __launch_bounds__(256, 2) adj_sym_kernel(
    const float* __restrict__ A,
    float*       __restrict__ C,
    int M, int Kd)
{
    extern __shared__ __align__(16) float smem_pool[];

    const int by = blockIdx.y, bx = blockIdx.x;
    if (bx < by) return;                 // symmetric: upper-triangular tiles

    // phase-1 aliases
    float (*As)[GT_BK][GT_TM] = reinterpret_cast<float (*)[GT_BK][GT_TM]>(smem_pool);
    float (*Bs)[GT_BK][GT_TM] =
        reinterpret_cast<float (*)[GT_BK][GT_TM]>(smem_pool + 2 * GT_BK * GT_TM);

    const int tid = threadIdx.x;
    const int bm  = by * GT_TM;
    const int bn  = bx * GT_TM;
    const int tx  = tid & 15;
    const int ty  = tid >> 4;

    float acc[8][8];
#pragma unroll
    for (int i = 0; i < 8; i++)
#pragma unroll
        for (int j = 0; j < 8; j++) acc[i][j] = 0.0f;

    auto stage = [&](int buf, int k0) {
#pragma unroll
        for (int s = 0; s < 2; s++) {
            const int f  = tid + s * 256;
            const int r  = f >> 2;
            const int kq = (f & 3) << 2;
            const int ga = bm + r;
            float4 va = make_float4(0.f, 0.f, 0.f, 0.f);
            if (ga < M)
                va = *reinterpret_cast<const float4*>(A + (size_t)ga * Kd + k0 + kq);
            As[buf][kq + 0][r] = va.x; As[buf][kq + 1][r] = va.y;
            As[buf][kq + 2][r] = va.z; As[buf][kq + 3][r] = va.w;

            const int gb = bn + r;
            float4 vb = make_float4(0.f, 0.f, 0.f, 0.f);
            if (gb < M)
                vb = *reinterpret_cast<const float4*>(A + (size_t)gb * Kd + k0 + kq);
            Bs[buf][kq + 0][r] = vb.x; Bs[buf][kq + 1][r] = vb.y;
            Bs[buf][kq + 2][r] = vb.z; Bs[buf][kq + 3][r] = vb.w;
        }
    };

    stage(0, 0);
    __syncthreads();

    const int nk = Kd / GT_BK;
    for (int kt = 0; kt < nk; kt++) {
        const int cur = kt & 1;
        if (kt + 1 < nk) stage(cur ^ 1, (kt + 1) * GT_BK);

#pragma unroll
        for (int kk = 0; kk < GT_BK; kk++) {
            float a[8], b[8];
#pragma unroll
            for (int i = 0; i < 8; i += 4)
                *reinterpret_cast<float4*>(&a[i]) =
                    *reinterpret_cast<const float4*>(&As[cur][kk][ty * 8 + i]);
#pragma unroll
            for (int j = 0; j < 8; j += 4)
                *reinterpret_cast<float4*>(&b[j]) =
                    *reinterpret_cast<const float4*>(&Bs[cur][kk][tx * 8 + j]);
#pragma unroll
            for (int i = 0; i < 8; i++)
#pragma unroll
                for (int j = 0; j < 8; j++)
                    acc[i][j] = fmaf(a[i], b[j], acc[i][j]);
        }
        __syncthreads();
    }

    // ---- epilogue: direct tile (coalesced) + stage into SMEM transpose ----
    float* Ct = smem_pool;                       // [128][133]
#define CT(r, c) Ct[(r) * 133 + (c)]

#pragma unroll
    for (int i = 0; i < 8; i++) {
        const int r0 = ty * 8 + i;
        const int gr = bm + r0;
#pragma unroll
        for (int j = 0; j < 8; j += 4) {
            const int c0 = tx * 8 + j;
            const float v0 = acc[i][j + 0], v1 = acc[i][j + 1];
            const float v2 = acc[i][j + 2], v3 = acc[i][j + 3];
            CT(r0, c0 + 0) = v0; CT(r0, c0 + 1) = v1;
            CT(r0, c0 + 2) = v2; CT(r0, c0 + 3) = v3;

            if (gr < M) {
                const int gc = bn + c0;
                if (gc + 3 < M) {
                    *reinterpret_cast<float4*>(C + (size_t)gr * M + gc) =
                        make_float4(v0, v1, v2, v3);
                } else {
                    const float vv[4] = {v0, v1, v2, v3};
                    for (int q = 0; q < 4; q++)
                        if (gc + q < M) C[(size_t)gr * M + gc + q] = vv[q];
                }
            }
        }
    }
    __syncthreads();

    // mirror tile (coalesced rows of C; conflict-free SMEM column reads)
    for (int i = tid; i < 128 * 128; i += 256) {
        const int r2 = i >> 7;          // tile column -> output row
        const int c2 = i & 127;         // tile row    -> output col
        const int gR = bn + r2, gC = bm + c2;
        if (gR < M && gC < M)
            C[(size_t)gR * M + gC] = CT(c2, r2);
    }
#undef CT
}

// ---------------------------------------------------------------------------
// Kernel 4: per-row top-K mask, in place on adj (radix select, exact ties).
// ---------------------------------------------------------------------------
__global__ void __launch_bounds__(256) topk_mask_kernel(float* __restrict__ adj, int N)
{
    __shared__ float    s_val[NNODES];
    __shared__ unsigned s_hist[256];
    __shared__ unsigned s_prefix;
    __shared__ int      s_rank, s_cnt;

    const int    tid  = threadIdx.x;
    const size_t base = (size_t)blockIdx.x * N;

    for (int j = tid; j < N; j += 256) s_val[j] = adj[base + j];
    __syncthreads();

    unsigned prefix = 0u;
    int      rank   = TOPK;
    int      cnt_eq = 0;

    for (int shift = 24; shift >= 0; shift -= 8) {
        s_hist[tid & 255] = 0;
        __syncthreads();

        const unsigned hmask = (shift == 24) ? 0u : (0xFFFFFFFFu << (shift + 8));
        for (int j = tid; j < N; j += 256) {
            const unsigned k = __float_as_uint(s_val[j]);
            if ((k & hmask) == prefix)
                atomicAdd(&s_hist[(k >> shift) & 0xFF], 1u);
        }
        __syncthreads();

        if (tid == 0) {
            int r = rank;
            int b = 255;
            for (;; b--) {
                const int h = (int)s_hist[b];
                if (h >= r || b == 0) { s_cnt = h; break; }
                r -= h;
            }
            s_prefix = prefix | ((unsigned)b << shift);
            s_rank   = r;
        }
        __syncthreads();
        prefix = s_prefix;
        rank   = s_rank;
        cnt_eq = s_cnt;
        __syncthreads();
    }

    const float Tval = __uint_as_float(prefix);

    if (cnt_eq > rank) {
        if (tid == 0) {
            int kept = 0;
            for (int j = 0; j < N; j++) {
                if (__float_as_uint(s_val[j]) == prefix) {
                    kept++;
                    if (kept > rank) s_val[j] = -1.0f;
                }
            }
        }
        __syncthreads();
    }

    for (int j = tid; j < N; j += 256) {
        const float v = s_val[j];
        adj[base + j] = (v >= Tval) ? v : 0.0f;
    }
}

// ---------------------------------------------------------------------------
// kernel_launch
// ---------------------------------------------------------------------------
extern "C" void kernel_launch(void* const* d_in, const int* in_sizes, int n_in,
                              void* d_out, int out_size)
{
    (void)in_sizes; (void)n_in; (void)out_size;

    const int*   idx   = (const int*)  d_in[0];
    const float* embn  = (const float*)d_in[1];
    const float* embhe = (const float*)d_in[2];
    const float* W1    = (const float*)d_in[3];
    const float* b1    = (const float*)d_in[4];
    const float* W2    = (const float*)d_in[5];
    const float* b2    = (const float*)d_in[6];
    float*       out   = (float*)d_out;

    float *p_nv1 = nullptr, *p_nv2 = nullptr, *p_H = nullptr;
    cudaGetSymbolAddress((void**)&p_nv1, g_nv1);
    cudaGetSymbolAddress((void**)&p_nv2, g_nv2);
    cudaGetSymbolAddress((void**)&p_H,   g_H);

    cudaFuncSetAttribute(adj_sym_kernel,
                         cudaFuncAttributeMaxDynamicSharedMemorySize,
                         ADJ_SMEM_BYTES);

    // 1) nodevecs
    nodevec_kernel<<<NNODES, EDIM>>>(embn, idx, W1, b1, p_nv1);
    nodevec_kernel<<<NHEDGES, EDIM>>>(embhe, nullptr, W2, b2, p_nv2);

    // 2) H = relu(tanh(3 * nv1 @ nv2^T))   [10000,512]
    {
        dim3 grid((NHEDGES + GT_TM - 1) / GT_TM, (NNODES + GT_TM - 1) / GT_TM);
        h_gemm_kernel<<<grid, 256>>>(p_nv1, p_nv2, p_H, NNODES, NHEDGES, EDIM);
    }

    // 3) adj = H @ H^T (bit-identical accumulation to R1; symmetric tiles)
    {
        const int nt = (NNODES + GT_TM - 1) / GT_TM;   // 79
        dim3 grid(nt, nt);
        adj_sym_kernel<<<grid, 256, ADJ_SMEM_BYTES>>>(p_H, out, NNODES, NHEDGES);
    }

    // 4) per-row top-32 mask, in place
    topk_mask_kernel<<<NNODES, 256>>>(out, NNODES);
}